// round 7
// baseline (speedup 1.0000x reference)
#include <cuda_runtime.h>
#include <math.h>
#include <stdint.h>

// Problem constants (fixed shapes)
#define BQ 4
#define LQ 4096
#define DQ 512
#define NQ 64
#define MQ (BQ * LQ)        // 16384 rows
#define NBLK 256            // (b,chunk) blocks, chunk=64

typedef unsigned long long ull;

// -------- scratch (device globals; no allocation allowed) --------
__device__ float g_xp[(size_t)MQ * 1024];        // xproj out: x_bar [0,512), z [512,1024)
__device__ float g_xt[(size_t)MQ * 512];         // tf32-rounded x (k-permuted)
__device__ float g_xbt[(size_t)MQ * 512];        // tf32-rounded x_bar (k-permuted)
__device__ float g_Bm[(size_t)MQ * 64];          // B proj (rmsnormed)
__device__ float g_Cm[(size_t)MQ * 64];          // C proj (rmsnormed)
__device__ float g_ax[(size_t)MQ * 512];         // a=exp(la); overwritten w/ cumulative decay
__device__ float g_Yb[(size_t)MQ * 512];         // y buffer (h stored tf32-rounded, k-permuted)
__device__ float g_cs[(size_t)NBLK * 64 * 512];  // chunk states -> prev states
__device__ float g_dtot[(size_t)NBLK * 512];     // per-chunk total decay
__device__ float g_Ac[512];                      // A coefficient
// transposed tf32 weights: Wt[n][k], k contiguous 512, k-permuted per 8-group
__device__ float g_Wt_xp[1024 * 512];
__device__ float g_Wt_dt[512 * 512];
__device__ float g_Wt_out[512 * 512];
__device__ float g_Wt_bc[128 * 512];             // rows 0..63 = W_B^T, 64..127 = W_C^T

// ============================ helpers ============================
__device__ __forceinline__ int perm8(int k) { return (k < 4) ? 2 * k : 2 * k - 7; }

__device__ __forceinline__ uint32_t f2tf32(float x) {
    uint32_t u;
    asm("cvt.rna.tf32.f32 %0, %1;" : "=r"(u) : "f"(x));
    return u;
}
__device__ __forceinline__ void mma_tf32(float* d, uint32_t a0, uint32_t a1,
                                         uint32_t a2, uint32_t a3,
                                         uint32_t b0, uint32_t b1) {
    asm volatile(
        "mma.sync.aligned.m16n8k8.row.col.f32.tf32.tf32.f32 "
        "{%0,%1,%2,%3}, {%4,%5,%6,%7}, {%8,%9}, {%0,%1,%2,%3};"
        : "+f"(d[0]), "+f"(d[1]), "+f"(d[2]), "+f"(d[3])
        : "r"(a0), "r"(a1), "r"(a2), "r"(a3), "r"(b0), "r"(b1));
}
__device__ __forceinline__ float dt_transform(float v, float Acoef) {
    float sp  = (v > 20.0f) ? v : log1pf(expf(v));
    float dtv = fminf(fmaxf(sp, 1e-4f), 5.0f);
    float la  = fminf(fmaxf(dtv * Acoef, -18.4206807f), 0.0f);
    return expf(la);
}
__device__ __forceinline__ void cpasync16(uint32_t saddr, const void* g) {
    asm volatile("cp.async.cg.shared.global [%0], [%1], 16;" :: "r"(saddr), "l"(g));
}
#define CP_COMMIT() asm volatile("cp.async.commit_group;" ::: "memory")
#define CP_WAIT1()  asm volatile("cp.async.wait_group 1;" ::: "memory")
#define CP_WAIT0()  asm volatile("cp.async.wait_group 0;" ::: "memory")

__device__ __forceinline__ ull pack2(float lo, float hi) {
    ull r; asm("mov.b64 %0, {%1, %2};" : "=l"(r) : "f"(lo), "f"(hi)); return r;
}
__device__ __forceinline__ void unpack2(ull v, float& lo, float& hi) {
    asm("mov.b64 {%0, %1}, %2;" : "=f"(lo), "=f"(hi) : "l"(v));
}
#define FMA2_ACC(d, a, b) \
    asm("fma.rn.f32x2 %0, %1, %2, %0;" : "+l"(d) : "l"(a), "l"(b))
#define MUL2(d, a, b) \
    asm("mul.rn.f32x2 %0, %1, %2;" : "=l"(d) : "l"(a), "l"(b))

// ============================ GEMM mainloop ============================
// D[128,128] tile = A[row0..+128, 0..512) * Bt[col0..+128, 0..512)^T.
// A and Bt are tf32-prerounded, k-permuted per 8-group ([0,4,1,5,2,6,3,7]).
// 8 warps (2 M x 4 N), warp tile 64x32, m16n8k8; fragment pairs via LDS.64.
#define STG_F (128 * 36)

__device__ __forceinline__ void gemm_mainloop(
    const float* __restrict__ A, const float* __restrict__ Bt,
    int row0, int col0, float* sm, float acc[4][4][4],
    int tid, int warp_m, int warp_n, int g, int tig)
{
    float* Asm = sm;                 // 2 stages x 128x36
    float* Bsm = sm + 2 * STG_F;
    const uint32_t asm_u = (uint32_t)__cvta_generic_to_shared(Asm);
    const uint32_t bsm_u = (uint32_t)__cvta_generic_to_shared(Bsm);
    const int ldm = tid >> 3;
    const int ldk4 = tid & 7;

    auto issue = [&](int s, int k0) {
        #pragma unroll
        for (int j = 0; j < 4; j++) {
            const int m = ldm + 32 * j;
            const uint32_t off = (uint32_t)((s * STG_F + m * 36 + ldk4 * 4) * 4);
            cpasync16(asm_u + off, &A[(size_t)(row0 + m) * 512 + k0 + ldk4 * 4]);
            cpasync16(bsm_u + off, &Bt[(size_t)(col0 + m) * 512 + k0 + ldk4 * 4]);
        }
        CP_COMMIT();
    };
    issue(0, 0);
    issue(1, 32);

    #pragma unroll 1
    for (int c = 0; c < 16; c++) {
        const int s = c & 1;
        if (c < 15) { CP_WAIT1(); } else { CP_WAIT0(); }
        __syncthreads();
        const uint32_t* AsU = (const uint32_t*)(Asm + s * STG_F);
        const uint32_t* BsU = (const uint32_t*)(Bsm + s * STG_F);
        #pragma unroll
        for (int kk = 0; kk < 4; kk++) {
            const int k = kk * 8 + 2 * tig;   // permuted: (lo,hi) = cols (tig, tig+4)
            uint2 a0[4], a1[4];
            #pragma unroll
            for (int mi = 0; mi < 4; mi++) {
                const int mr = warp_m * 64 + mi * 16 + g;
                a0[mi] = *(const uint2*)&AsU[mr * 36 + k];
                a1[mi] = *(const uint2*)&AsU[(mr + 8) * 36 + k];
            }
            #pragma unroll
            for (int ni = 0; ni < 4; ni++) {
                const int nr = warp_n * 32 + ni * 8 + g;
                const uint2 b = *(const uint2*)&BsU[nr * 36 + k];
                #pragma unroll
                for (int mi = 0; mi < 4; mi++)
                    mma_tf32(acc[mi][ni], a0[mi].x, a1[mi].x, a0[mi].y, a1[mi].y,
                             b.x, b.y);
            }
        }
        __syncthreads();
        if (c + 2 < 16) issue(s, (c + 2) * 32);
    }
}

// ---- EPI 0: +bias -> out0.  EPI 3: xproj (+bias -> out0 ld 1024; cols<512 also
//      tf32-rounded k-permuted -> out1 ld 512)
template <int EPI>
__global__ void __launch_bounds__(256, 2)
mma_gemm_k(const float* __restrict__ A,
           const float* __restrict__ Bt,
           const float* __restrict__ bias,
           float* __restrict__ out0, float* __restrict__ out1, int ldc)
{
    extern __shared__ float sm[];
    const int tid = threadIdx.x;
    const int wid = tid >> 5;
    const int lane = tid & 31;
    const int g = lane >> 2;
    const int tig = lane & 3;
    const int warp_m = wid >> 2;
    const int warp_n = wid & 3;
    const int row0 = blockIdx.y * 128;
    const int col0 = blockIdx.x * 128;

    float acc[4][4][4] = {};
    gemm_mainloop(A, Bt, row0, col0, sm, acc, tid, warp_m, warp_n, g, tig);

    const int p0 = (tig < 2) ? 4 * tig : 4 * tig - 7;   // perm8(2*tig)
    #pragma unroll
    for (int mi = 0; mi < 4; mi++) {
        const int m = row0 + warp_m * 64 + mi * 16 + g;
        #pragma unroll
        for (int ni = 0; ni < 4; ni++) {
            const int n = col0 + warp_n * 32 + ni * 8 + 2 * tig;
            float d0 = acc[mi][ni][0], d1 = acc[mi][ni][1];
            float d2 = acc[mi][ni][2], d3 = acc[mi][ni][3];
            const float b0 = bias[n], b1 = bias[n + 1];
            d0 += b0; d1 += b1; d2 += b0; d3 += b1;
            *(float2*)&out0[(size_t)m * ldc + n] = make_float2(d0, d1);
            *(float2*)&out0[(size_t)(m + 8) * ldc + n] = make_float2(d2, d3);
            if (EPI == 3 && n < 512) {
                const size_t base = (size_t)m * 512 + (n - 2 * tig);
                out1[base + p0]     = __uint_as_float(f2tf32(d0));
                out1[base + p0 + 2] = __uint_as_float(f2tf32(d1));
                out1[base + 8 * 512 + p0]     = __uint_as_float(f2tf32(d2));
                out1[base + 8 * 512 + p0 + 2] = __uint_as_float(f2tf32(d3));
            }
        }
    }
}

// ---- merged dt (blockIdx.x<4) + fused B|C rmsnorm (blockIdx.x==4) ----
__global__ void __launch_bounds__(256, 2)
dtbc_gemm_k(const float* __restrict__ xbt,
            const float* __restrict__ Wdt, const float* __restrict__ Wbc,
            const float* __restrict__ dt_bias, const float* __restrict__ Ac,
            float* __restrict__ ax,
            float* __restrict__ Bm, float* __restrict__ Cm,
            const float* __restrict__ gBn, const float* __restrict__ gCn)
{
    extern __shared__ float sm[];
    __shared__ float ssred[256];
    const int tid = threadIdx.x;
    const int wid = tid >> 5;
    const int lane = tid & 31;
    const int g = lane >> 2;
    const int tig = lane & 3;
    const int warp_m = wid >> 2;
    const int warp_n = wid & 3;
    const int row0 = blockIdx.y * 128;
    const bool is_dt = blockIdx.x < 4;
    const int col0 = is_dt ? blockIdx.x * 128 : 0;
    const float* Bt = is_dt ? Wdt : Wbc;

    if (!is_dt) ssred[tid] = 0.0f;

    float acc[4][4][4] = {};
    gemm_mainloop(xbt, Bt, row0, col0, sm, acc, tid, warp_m, warp_n, g, tig);

    if (is_dt) {
        #pragma unroll
        for (int mi = 0; mi < 4; mi++) {
            const int m = row0 + warp_m * 64 + mi * 16 + g;
            #pragma unroll
            for (int ni = 0; ni < 4; ni++) {
                const int n = col0 + warp_n * 32 + ni * 8 + 2 * tig;
                const float b0 = dt_bias[n], b1 = dt_bias[n + 1];
                const float a0 = Ac[n], a1 = Ac[n + 1];
                *(float2*)&ax[(size_t)m * 512 + n] = make_float2(
                    dt_transform(acc[mi][ni][0] + b0, a0),
                    dt_transform(acc[mi][ni][1] + b1, a1));
                *(float2*)&ax[(size_t)(m + 8) * 512 + n] = make_float2(
                    dt_transform(acc[mi][ni][2] + b0, a0),
                    dt_transform(acc[mi][ni][3] + b1, a1));
            }
        }
    } else {
        const int half = warp_n >> 1;                 // 0 = B, 1 = C
        #pragma unroll
        for (int mi = 0; mi < 4; mi++) {
            float s0 = 0.0f, s1 = 0.0f;
            #pragma unroll
            for (int ni = 0; ni < 4; ni++) {
                s0 += acc[mi][ni][0] * acc[mi][ni][0] + acc[mi][ni][1] * acc[mi][ni][1];
                s1 += acc[mi][ni][2] * acc[mi][ni][2] + acc[mi][ni][3] * acc[mi][ni][3];
            }
            s0 += __shfl_xor_sync(0xffffffffu, s0, 1);
            s0 += __shfl_xor_sync(0xffffffffu, s0, 2);
            s1 += __shfl_xor_sync(0xffffffffu, s1, 1);
            s1 += __shfl_xor_sync(0xffffffffu, s1, 2);
            if (tig == 0) {
                const int r = warp_m * 64 + mi * 16 + g;
                atomicAdd(&ssred[half * 128 + r], s0);
                atomicAdd(&ssred[half * 128 + r + 8], s1);
            }
        }
        __syncthreads();
        const float* gam = half ? gCn : gBn;
        float* outp = half ? Cm : Bm;
        #pragma unroll
        for (int mi = 0; mi < 4; mi++) {
            const int r = warp_m * 64 + mi * 16 + g;
            const float rs0 = rsqrtf(ssred[half * 128 + r] * (1.0f / 64.0f) + 1e-6f);
            const float rs1 = rsqrtf(ssred[half * 128 + r + 8] * (1.0f / 64.0f) + 1e-6f);
            #pragma unroll
            for (int ni = 0; ni < 4; ni++) {
                const int nl = (warp_n - half * 2) * 32 + ni * 8 + 2 * tig;  // 0..63
                const float g0 = gam[nl], g1 = gam[nl + 1];
                *(float2*)&outp[(size_t)(row0 + r) * 64 + nl] =
                    make_float2(acc[mi][ni][0] * rs0 * g0, acc[mi][ni][1] * rs0 * g1);
                *(float2*)&outp[(size_t)(row0 + r + 8) * 64 + nl] =
                    make_float2(acc[mi][ni][2] * rs1 * g0, acc[mi][ni][3] * rs1 * g1);
            }
        }
    }
}

// ============================ prep kernels ============================

__global__ void acoef_k(const float* __restrict__ A_log, float* __restrict__ Ac)
{
    int d = threadIdx.x;
    Ac[d] = -expf(fminf(fmaxf(A_log[d], -20.0f), 2.0f));
}

// [0,4096): round x -> xt, k-permuted (8 floats/thread).
// [4096,5184): weight transposes + cvt + k-permute.
__global__ void __launch_bounds__(256)
prep_k(const float* __restrict__ x,
       const float* __restrict__ Wxp, const float* __restrict__ Wdt,
       const float* __restrict__ Wout, const float* __restrict__ WB,
       const float* __restrict__ WC,
       float* __restrict__ xt, float* __restrict__ Twxp, float* __restrict__ Twdt,
       float* __restrict__ Twout, float* __restrict__ Twbc)
{
    int bid = blockIdx.x;
    if (bid < 4096) {
        const size_t gi = (size_t)bid * 256 + threadIdx.x;   // 8-float group index
        float4 v0 = ((const float4*)x)[gi * 2];
        float4 v1 = ((const float4*)x)[gi * 2 + 1];
        // permuted: [x0,x4,x1,x5 | x2,x6,x3,x7]
        ((uint4*)xt)[gi * 2]     = make_uint4(f2tf32(v0.x), f2tf32(v1.x),
                                              f2tf32(v0.y), f2tf32(v1.y));
        ((uint4*)xt)[gi * 2 + 1] = make_uint4(f2tf32(v0.z), f2tf32(v1.z),
                                              f2tf32(v0.w), f2tf32(v1.w));
        return;
    }
    bid -= 4096;
    const float* W; float* Wt; int N, lb;
    if (bid < 512)       { W = Wxp;  Wt = Twxp;            N = 1024; lb = bid; }
    else if (bid < 768)  { W = Wdt;  Wt = Twdt;            N = 512;  lb = bid - 512; }
    else if (bid < 1024) { W = Wout; Wt = Twout;           N = 512;  lb = bid - 768; }
    else if (bid < 1056) { W = WB;   Wt = Twbc;            N = 64;   lb = bid - 1024; }
    else                 { W = WC;   Wt = Twbc + 64 * 512; N = 64;   lb = bid - 1056; }
    const int tiles_n = N / 32;
    const int n0 = (lb % tiles_n) * 32;
    const int k0 = (lb / tiles_n) * 32;
    __shared__ float tile[32][33];
    const int tx = threadIdx.x & 31, ty = threadIdx.x >> 5;
    for (int i = ty; i < 32; i += 8)
        tile[i][tx] = W[(size_t)(k0 + i) * N + n0 + tx];
    __syncthreads();
    const int kp = k0 + 8 * (tx >> 3) + perm8(tx & 7);
    for (int i = ty; i < 32; i += 8)
        Wt[(size_t)(n0 + i) * 512 + kp] = __uint_as_float(f2tf32(tile[tx][i]));
}

// ============================ scan kernels ============================

// Intra-chunk recurrence (f32x2, prefetch). Y gets y_intra + D_skip*x_bar.
__global__ void __launch_bounds__(512)
scan_intra_k(const float* __restrict__ xp, const float* __restrict__ Bm,
             const float* __restrict__ Cm, const float* __restrict__ Dskip,
             float* __restrict__ ax, float* __restrict__ Y,
             float* __restrict__ cs, float* __restrict__ dtot)
{
    __shared__ float4 Bs[64][16];
    __shared__ float4 Cs[64][16];
    const int blk = blockIdx.x;
    const int d = threadIdx.x;
    const size_t l0 = (size_t)blk * 64;

    for (int t = d; t < 64 * 16; t += 512) {
        int r = t >> 4, c = t & 15;
        Bs[r][c] = ((const float4*)Bm)[(l0 + r) * 16 + c];
        Cs[r][c] = ((const float4*)Cm)[(l0 + r) * 16 + c];
    }
    __syncthreads();

    ull S2[32];
    #pragma unroll
    for (int q = 0; q < 32; q++) S2[q] = 0ull;
    float dec = 1.0f;
    const float dsk = Dskip[d];

    const float* axp = ax + l0 * 512 + d;
    const float* xpp = xp + l0 * 1024 + d;
    float av = axp[0];
    float xv = xpp[0];

    #pragma unroll 1
    for (int i = 0; i < 64; i++) {
        float av_n = 0.0f, xv_n = 0.0f;
        if (i < 63) { av_n = axp[(size_t)(i + 1) * 512]; xv_n = xpp[(size_t)(i + 1) * 1024]; }
        const size_t m = l0 + i;
        dec *= av;
        ax[m * 512 + d] = dec;
        const ull av2 = pack2(av, av);
        const ull xv2 = pack2(xv, xv);
        const ull* Bp = (const ull*)&Bs[i][0];
        const ull* Cp = (const ull*)&Cs[i][0];
        ull y2 = 0ull;
        #pragma unroll
        for (int q = 0; q < 32; q++) {
            ull bx; MUL2(bx, Bp[q], xv2);
            FMA2_ACC(bx, av2, S2[q]);   // bx = av*S + b*x
            S2[q] = bx;
            FMA2_ACC(y2, Cp[q], S2[q]);
        }
        float ylo, yhi; unpack2(y2, ylo, yhi);
        Y[m * 512 + d] = ylo + yhi + dsk * xv;
        av = av_n; xv = xv_n;
    }

    #pragma unroll
    for (int q = 0; q < 32; q++) {
        float slo, shi; unpack2(S2[q], slo, shi);
        cs[((size_t)blk * 64 + 2 * q) * 512 + d] = slo;
        cs[((size_t)blk * 64 + 2 * q + 1) * 512 + d] = shi;
    }
    dtot[(size_t)blk * 512 + d] = dec;
}

// Inter-chunk state scan (prefetch), float4 over d; cs -> prev_state in place.
__global__ void state_scan_k(float* __restrict__ cs, const float* __restrict__ dtot)
{
    const int idx = blockIdx.x * blockDim.x + threadIdx.x;   // B*N*128 = 32768
    const int d4 = idx & 127;
    const int n = (idx >> 7) & 63;
    const int b = idx >> 13;
    float4* cs4 = (float4*)cs;
    const float4* dt4 = (const float4*)dtot;
    float4 s = make_float4(0.f, 0.f, 0.f, 0.f);

    size_t off = ((size_t)(b * 64) * 64 + n) * 128 + d4;
    float4 v = cs4[off];
    float4 a = dt4[(size_t)(b * 64) * 128 + d4];

    #pragma unroll 1
    for (int ch = 0; ch < 64; ch++) {
        float4 vn, an;
        if (ch < 63) {
            const int blkn = b * 64 + ch + 1;
            vn = cs4[((size_t)blkn * 64 + n) * 128 + d4];
            an = dt4[(size_t)blkn * 128 + d4];
        } else { vn = s; an = s; }
        cs4[off] = s;
        s.x = fmaf(s.x, a.x, v.x);
        s.y = fmaf(s.y, a.y, v.y);
        s.z = fmaf(s.z, a.z, v.z);
        s.w = fmaf(s.w, a.w, v.w);
        off = ((size_t)(b * 64 + ch + 1) * 64 + n) * 128 + d4;
        v = vn; a = an;
    }
}

// y += decay * (C @ prev_state)   (f32x2; D_skip already folded in scan_intra)
__global__ void __launch_bounds__(512)
yinter_k(const float* __restrict__ Cm, const float* __restrict__ ps,
         const float* __restrict__ decay, float* __restrict__ Y)
{
    __shared__ float4 Cs[64][16];
    const int blk = blockIdx.x;
    const int d = threadIdx.x;
    const size_t l0 = (size_t)blk * 64;

    for (int t = d; t < 64 * 16; t += 512) {
        int r = t >> 4, c = t & 15;
        Cs[r][c] = ((const float4*)Cm)[(l0 + r) * 16 + c];
    }
    __syncthreads();

    ull PS2[32];
    #pragma unroll
    for (int q = 0; q < 32; q++)
        PS2[q] = pack2(ps[((size_t)blk * 64 + 2 * q) * 512 + d],
                       ps[((size_t)blk * 64 + 2 * q + 1) * 512 + d]);

    float dc = decay[l0 * 512 + d];
    float yv = Y[l0 * 512 + d];

    #pragma unroll 1
    for (int i = 0; i < 64; i++) {
        float dc_n = 0.0f, yv_n = 0.0f;
        if (i < 63) {
            dc_n = decay[(l0 + i + 1) * 512 + d];
            yv_n = Y[(l0 + i + 1) * 512 + d];
        }
        const ull* Cp = (const ull*)&Cs[i][0];
        ull y2 = 0ull;
        #pragma unroll
        for (int q = 0; q < 32; q++)
            FMA2_ACC(y2, Cp[q], PS2[q]);
        float ylo, yhi; unpack2(y2, ylo, yhi);
        Y[(l0 + i) * 512 + d] = yv + dc * (ylo + yhi);
        dc = dc_n; yv = yv_n;
    }
}

// h = tf32round(rmsnorm(y, g) * silu(z)), k-permuted store, in place over Y.
__global__ void outnorm_k(float* __restrict__ Y, const float* __restrict__ xp,
                          const float* __restrict__ g)
{
    __shared__ float red[256];
    const int m = blockIdx.x;
    const int t = threadIdx.x;
    float v0 = Y[(size_t)m * 512 + t];
    float v1 = Y[(size_t)m * 512 + t + 256];
    red[t] = v0 * v0 + v1 * v1;
    __syncthreads();
    for (int s = 128; s > 0; s >>= 1) {
        if (t < s) red[t] += red[t + s];
        __syncthreads();
    }
    float rs = rsqrtf(red[0] * (1.0f / 512.0f) + 1e-6f);
    float z0 = xp[(size_t)m * 1024 + 512 + t];
    float z1 = xp[(size_t)m * 1024 + 512 + t + 256];
    float s0 = z0 / (1.0f + expf(-z0));
    float s1 = z1 / (1.0f + expf(-z1));
    const int pd = (t & ~7) + perm8(t & 7);
    Y[(size_t)m * 512 + pd]       = __uint_as_float(f2tf32(v0 * rs * g[t] * s0));
    Y[(size_t)m * 512 + pd + 256] = __uint_as_float(f2tf32(v1 * rs * g[t + 256] * s1));
}

// ============================ launch ============================
#define GEMM_SMEM 73728

extern "C" void kernel_launch(void* const* d_in, const int* in_sizes, int n_in,
                              void* d_out, int out_size)
{
    const float* x       = (const float*)d_in[0];
    const float* A_log   = (const float*)d_in[1];
    const float* dt_bias = (const float*)d_in[2];
    const float* D_skip  = (const float*)d_in[3];
    const float* W_xproj = (const float*)d_in[4];
    const float* b_xproj = (const float*)d_in[5];
    const float* W_B     = (const float*)d_in[6];
    const float* W_C     = (const float*)d_in[7];
    const float* W_dt    = (const float*)d_in[8];
    const float* g_Bn    = (const float*)d_in[9];
    const float* g_Cn    = (const float*)d_in[10];
    const float* g_on    = (const float*)d_in[11];
    const float* W_out   = (const float*)d_in[12];
    const float* b_out   = (const float*)d_in[13];
    float* out = (float*)d_out;

    float *p_xp, *p_xt, *p_xbt, *p_Bm, *p_Cm, *p_ax, *p_Y, *p_cs, *p_dt, *p_Ac;
    float *p_Wxp, *p_Wdt, *p_Wout, *p_Wbc;
    cudaGetSymbolAddress((void**)&p_xp,  g_xp);
    cudaGetSymbolAddress((void**)&p_xt,  g_xt);
    cudaGetSymbolAddress((void**)&p_xbt, g_xbt);
    cudaGetSymbolAddress((void**)&p_Bm,  g_Bm);
    cudaGetSymbolAddress((void**)&p_Cm,  g_Cm);
    cudaGetSymbolAddress((void**)&p_ax,  g_ax);
    cudaGetSymbolAddress((void**)&p_Y,   g_Yb);
    cudaGetSymbolAddress((void**)&p_cs,  g_cs);
    cudaGetSymbolAddress((void**)&p_dt,  g_dtot);
    cudaGetSymbolAddress((void**)&p_Ac,  g_Ac);
    cudaGetSymbolAddress((void**)&p_Wxp,  g_Wt_xp);
    cudaGetSymbolAddress((void**)&p_Wdt,  g_Wt_dt);
    cudaGetSymbolAddress((void**)&p_Wout, g_Wt_out);
    cudaGetSymbolAddress((void**)&p_Wbc,  g_Wt_bc);

    cudaFuncSetAttribute(mma_gemm_k<0>, cudaFuncAttributeMaxDynamicSharedMemorySize, GEMM_SMEM);
    cudaFuncSetAttribute(mma_gemm_k<3>, cudaFuncAttributeMaxDynamicSharedMemorySize, GEMM_SMEM);
    cudaFuncSetAttribute(dtbc_gemm_k,   cudaFuncAttributeMaxDynamicSharedMemorySize, GEMM_SMEM);

    // 0: A coefficient
    acoef_k<<<1, 512>>>(A_log, p_Ac);
    // 1: weight transposes + x rounding (k-permuted)
    prep_k<<<5184, 256>>>(x, W_xproj, W_dt, W_out, W_B, W_C,
                          p_xt, p_Wxp, p_Wdt, p_Wout, p_Wbc);
    // 2: xp = x @ W_xproj + b_xproj (also emits tf32 k-permuted x_bar)
    mma_gemm_k<3><<<dim3(8, 128), 256, GEMM_SMEM>>>(
        p_xt, p_Wxp, b_xproj, p_xp, p_xbt, 1024);
    // 3: merged dt-GEMM + fused B|C projection + rmsnorm (one wave)
    dtbc_gemm_k<<<dim3(5, 128), 256, GEMM_SMEM>>>(
        p_xbt, p_Wdt, p_Wbc, dt_bias, p_Ac, p_ax, p_Bm, p_Cm, g_Bn, g_Cn);
    // 4: intra-chunk recurrence (+ D_skip*x_bar folded)
    scan_intra_k<<<NBLK, 512>>>(p_xp, p_Bm, p_Cm, D_skip, p_ax, p_Y, p_cs, p_dt);
    // 5: inter-chunk state scan
    state_scan_k<<<(BQ * NQ * 128) / 256, 256>>>(p_cs, p_dt);
    // 6: y += decay * (C @ prev_state)
    yinter_k<<<NBLK, 512>>>(p_Cm, p_cs, p_ax, p_Y);
    // 7: h = rmsnorm(y) * silu(z) (tf32, k-permuted)
    outnorm_k<<<MQ, 256>>>(p_Y, p_xp, g_on);
    // 8: out = h @ W_out + b_out
    mma_gemm_k<0><<<dim3(4, 128), 256, GEMM_SMEM>>>(
        p_Y, p_Wout, b_out, out, nullptr, 512);
}

// round 8
// speedup vs baseline: 1.6889x; 1.6889x over previous
#include <cuda_runtime.h>
#include <math.h>
#include <stdint.h>

// Problem constants (fixed shapes)
#define BQ 4
#define LQ 4096
#define DQ 512
#define NQ 64
#define MQ (BQ * LQ)        // 16384 rows
#define NBLK 256            // (b,chunk) blocks, chunk=64

typedef unsigned long long ull;

// -------- scratch (device globals; no allocation allowed) --------
__device__ float g_xp[(size_t)MQ * 1024];        // xproj out: x_bar [0,512), z [512,1024)
__device__ float g_xt[(size_t)MQ * 512];         // tf32-rounded x
__device__ float g_xbt[(size_t)MQ * 512];        // tf32-rounded x_bar
__device__ float g_Bm[(size_t)MQ * 64];          // B proj (rmsnormed)
__device__ float g_Cm[(size_t)MQ * 64];          // C proj (rmsnormed)
__device__ float g_ax[(size_t)MQ * 512];         // a=exp(la); overwritten w/ cumulative decay
__device__ float g_Yb[(size_t)MQ * 512];         // y buffer (h stored tf32-rounded)
__device__ float g_cs[(size_t)NBLK * 64 * 512];  // chunk states -> prev states
__device__ float g_dtot[(size_t)NBLK * 512];     // per-chunk total decay
__device__ float g_Ac[512];                      // A coefficient
// transposed tf32 weights: Wt[n][k], k contiguous (512)
__device__ float g_Wt_xp[1024 * 512];
__device__ float g_Wt_dt[512 * 512];
__device__ float g_Wt_out[512 * 512];
__device__ float g_Wt_bc[128 * 512];             // rows 0..63 = W_B^T, 64..127 = W_C^T

// ============================ helpers ============================
__device__ __forceinline__ uint32_t f2tf32(float x) {
    uint32_t u;
    asm("cvt.rna.tf32.f32 %0, %1;" : "=r"(u) : "f"(x));
    return u;
}
__device__ __forceinline__ void mma_tf32(float* d, const uint32_t* a, const uint32_t* b) {
    asm volatile(
        "mma.sync.aligned.m16n8k8.row.col.f32.tf32.tf32.f32 "
        "{%0,%1,%2,%3}, {%4,%5,%6,%7}, {%8,%9}, {%0,%1,%2,%3};"
        : "+f"(d[0]), "+f"(d[1]), "+f"(d[2]), "+f"(d[3])
        : "r"(a[0]), "r"(a[1]), "r"(a[2]), "r"(a[3]), "r"(b[0]), "r"(b[1]));
}
__device__ __forceinline__ float dt_transform(float v, float Acoef) {
    float sp  = (v > 20.0f) ? v : log1pf(expf(v));
    float dtv = fminf(fmaxf(sp, 1e-4f), 5.0f);
    float la  = fminf(fmaxf(dtv * Acoef, -18.4206807f), 0.0f);
    return expf(la);
}
__device__ __forceinline__ void cpasync16(uint32_t saddr, const void* g) {
    asm volatile("cp.async.cg.shared.global [%0], [%1], 16;" :: "r"(saddr), "l"(g));
}
#define CP_COMMIT() asm volatile("cp.async.commit_group;" ::: "memory")
#define CP_WAIT1()  asm volatile("cp.async.wait_group 1;" ::: "memory")
#define CP_WAIT0()  asm volatile("cp.async.wait_group 0;" ::: "memory")

__device__ __forceinline__ ull pack2(float lo, float hi) {
    ull r; asm("mov.b64 %0, {%1, %2};" : "=l"(r) : "f"(lo), "f"(hi)); return r;
}
__device__ __forceinline__ void unpack2(ull v, float& lo, float& hi) {
    asm("mov.b64 {%0, %1}, %2;" : "=f"(lo), "=f"(hi) : "l"(v));
}
#define FMA2_ACC(d, a, b) \
    asm("fma.rn.f32x2 %0, %1, %2, %0;" : "+l"(d) : "l"(a), "l"(b))
#define MUL2(d, a, b) \
    asm("mul.rn.f32x2 %0, %1, %2;" : "=l"(d) : "l"(a), "l"(b))

// ============================ GEMM mainloop (R6-proven) ============================
// D[128,128] tile = A[row0..+128, 0..512)(lda) * Bt[col0..+128, 0..512)^T.
// 8 warps (2 M x 4 N), warp tile 64x32, m16n8k8, scalar 32-bit LDS fragments.
#define STG_F (128 * 36)

__device__ __forceinline__ void gemm_mainloop(
    const float* __restrict__ A, int lda, const float* __restrict__ Bt,
    int row0, int col0, float* sm, float acc[4][4][4],
    int tid, int warp_m, int warp_n, int g, int tig)
{
    float* Asm = sm;                 // 2 stages x 128x36
    float* Bsm = sm + 2 * STG_F;
    const uint32_t asm_u = (uint32_t)__cvta_generic_to_shared(Asm);
    const uint32_t bsm_u = (uint32_t)__cvta_generic_to_shared(Bsm);
    const int ldm = tid >> 3;
    const int ldk4 = tid & 7;

    auto issue = [&](int s, int k0) {
        #pragma unroll
        for (int j = 0; j < 4; j++) {
            const int m = ldm + 32 * j;
            const uint32_t off = (uint32_t)((s * STG_F + m * 36 + ldk4 * 4) * 4);
            cpasync16(asm_u + off, &A[(size_t)(row0 + m) * lda + k0 + ldk4 * 4]);
            cpasync16(bsm_u + off, &Bt[(size_t)(col0 + m) * 512 + k0 + ldk4 * 4]);
        }
        CP_COMMIT();
    };
    issue(0, 0);
    issue(1, 32);

    #pragma unroll 1
    for (int c = 0; c < 16; c++) {
        const int s = c & 1;
        if (c < 15) { CP_WAIT1(); } else { CP_WAIT0(); }
        __syncthreads();
        const uint32_t* AsU = (const uint32_t*)(Asm + s * STG_F);
        const uint32_t* BsU = (const uint32_t*)(Bsm + s * STG_F);
        #pragma unroll
        for (int kk = 0; kk < 4; kk++) {
            const int k = kk * 8;
            uint32_t af[4][4];
            #pragma unroll
            for (int mi = 0; mi < 4; mi++) {
                const int mr = warp_m * 64 + mi * 16 + g;
                af[mi][0] = AsU[mr * 36 + k + tig];
                af[mi][1] = AsU[(mr + 8) * 36 + k + tig];
                af[mi][2] = AsU[mr * 36 + k + tig + 4];
                af[mi][3] = AsU[(mr + 8) * 36 + k + tig + 4];
            }
            #pragma unroll
            for (int ni = 0; ni < 4; ni++) {
                uint32_t bf[2];
                const int nr = warp_n * 32 + ni * 8 + g;
                bf[0] = BsU[nr * 36 + k + tig];
                bf[1] = BsU[nr * 36 + k + tig + 4];
                #pragma unroll
                for (int mi = 0; mi < 4; mi++)
                    mma_tf32(acc[mi][ni], af[mi], bf);
            }
        }
        __syncthreads();
        if (c + 2 < 16) issue(s, (c + 2) * 32);
    }
}

// ---- EPI 0: +bias -> out0.  EPI 3: xproj (+bias -> out0 ld 1024; cols<512 also
//      tf32-rounded -> out1 ld 512)
template <int EPI>
__global__ void __launch_bounds__(256, 2)
mma_gemm_k(const float* __restrict__ A, int lda,
           const float* __restrict__ Bt,
           const float* __restrict__ bias,
           float* __restrict__ out0, float* __restrict__ out1, int ldc)
{
    extern __shared__ float sm[];
    const int tid = threadIdx.x;
    const int wid = tid >> 5;
    const int lane = tid & 31;
    const int g = lane >> 2;
    const int tig = lane & 3;
    const int warp_m = wid >> 2;
    const int warp_n = wid & 3;
    const int row0 = blockIdx.y * 128;
    const int col0 = blockIdx.x * 128;

    float acc[4][4][4] = {};
    gemm_mainloop(A, lda, Bt, row0, col0, sm, acc, tid, warp_m, warp_n, g, tig);

    #pragma unroll
    for (int mi = 0; mi < 4; mi++) {
        const int m = row0 + warp_m * 64 + mi * 16 + g;
        #pragma unroll
        for (int ni = 0; ni < 4; ni++) {
            const int n = col0 + warp_n * 32 + ni * 8 + 2 * tig;
            float d0 = acc[mi][ni][0], d1 = acc[mi][ni][1];
            float d2 = acc[mi][ni][2], d3 = acc[mi][ni][3];
            const float b0 = bias[n], b1 = bias[n + 1];
            d0 += b0; d1 += b1; d2 += b0; d3 += b1;
            *(float2*)&out0[(size_t)m * ldc + n] = make_float2(d0, d1);
            *(float2*)&out0[(size_t)(m + 8) * ldc + n] = make_float2(d2, d3);
            if (EPI == 3 && n < 512) {
                *(float2*)&out1[(size_t)m * 512 + n] = make_float2(
                    __uint_as_float(f2tf32(d0)), __uint_as_float(f2tf32(d1)));
                *(float2*)&out1[(size_t)(m + 8) * 512 + n] = make_float2(
                    __uint_as_float(f2tf32(d2)), __uint_as_float(f2tf32(d3)));
            }
        }
    }
}

// ---- merged dt (blockIdx.x<4) + fused B|C rmsnorm (blockIdx.x==4) ----
__global__ void __launch_bounds__(256, 2)
dtbc_gemm_k(const float* __restrict__ xbt,
            const float* __restrict__ Wdt, const float* __restrict__ Wbc,
            const float* __restrict__ dt_bias, const float* __restrict__ Ac,
            float* __restrict__ ax,
            float* __restrict__ Bm, float* __restrict__ Cm,
            const float* __restrict__ gBn, const float* __restrict__ gCn)
{
    extern __shared__ float sm[];
    __shared__ float ssred[256];
    const int tid = threadIdx.x;
    const int wid = tid >> 5;
    const int lane = tid & 31;
    const int g = lane >> 2;
    const int tig = lane & 3;
    const int warp_m = wid >> 2;
    const int warp_n = wid & 3;
    const int row0 = blockIdx.y * 128;
    const bool is_dt = blockIdx.x < 4;
    const int col0 = is_dt ? blockIdx.x * 128 : 0;
    const float* Bt = is_dt ? Wdt : Wbc;

    if (!is_dt) ssred[tid] = 0.0f;

    float acc[4][4][4] = {};
    gemm_mainloop(xbt, 512, Bt, row0, col0, sm, acc, tid, warp_m, warp_n, g, tig);

    if (is_dt) {
        #pragma unroll
        for (int mi = 0; mi < 4; mi++) {
            const int m = row0 + warp_m * 64 + mi * 16 + g;
            #pragma unroll
            for (int ni = 0; ni < 4; ni++) {
                const int n = col0 + warp_n * 32 + ni * 8 + 2 * tig;
                const float b0 = dt_bias[n], b1 = dt_bias[n + 1];
                const float a0 = Ac[n], a1 = Ac[n + 1];
                *(float2*)&ax[(size_t)m * 512 + n] = make_float2(
                    dt_transform(acc[mi][ni][0] + b0, a0),
                    dt_transform(acc[mi][ni][1] + b1, a1));
                *(float2*)&ax[(size_t)(m + 8) * 512 + n] = make_float2(
                    dt_transform(acc[mi][ni][2] + b0, a0),
                    dt_transform(acc[mi][ni][3] + b1, a1));
            }
        }
    } else {
        const int half = warp_n >> 1;                 // 0 = B, 1 = C
        #pragma unroll
        for (int mi = 0; mi < 4; mi++) {
            float s0 = 0.0f, s1 = 0.0f;
            #pragma unroll
            for (int ni = 0; ni < 4; ni++) {
                s0 += acc[mi][ni][0] * acc[mi][ni][0] + acc[mi][ni][1] * acc[mi][ni][1];
                s1 += acc[mi][ni][2] * acc[mi][ni][2] + acc[mi][ni][3] * acc[mi][ni][3];
            }
            s0 += __shfl_xor_sync(0xffffffffu, s0, 1);
            s0 += __shfl_xor_sync(0xffffffffu, s0, 2);
            s1 += __shfl_xor_sync(0xffffffffu, s1, 1);
            s1 += __shfl_xor_sync(0xffffffffu, s1, 2);
            if (tig == 0) {
                const int r = warp_m * 64 + mi * 16 + g;
                atomicAdd(&ssred[half * 128 + r], s0);
                atomicAdd(&ssred[half * 128 + r + 8], s1);
            }
        }
        __syncthreads();
        const float* gam = half ? gCn : gBn;
        float* outp = half ? Cm : Bm;
        #pragma unroll
        for (int mi = 0; mi < 4; mi++) {
            const int r = warp_m * 64 + mi * 16 + g;
            const float rs0 = rsqrtf(ssred[half * 128 + r] * (1.0f / 64.0f) + 1e-6f);
            const float rs1 = rsqrtf(ssred[half * 128 + r + 8] * (1.0f / 64.0f) + 1e-6f);
            #pragma unroll
            for (int ni = 0; ni < 4; ni++) {
                const int nl = (warp_n - half * 2) * 32 + ni * 8 + 2 * tig;  // 0..63
                const float g0 = gam[nl], g1 = gam[nl + 1];
                *(float2*)&outp[(size_t)(row0 + r) * 64 + nl] =
                    make_float2(acc[mi][ni][0] * rs0 * g0, acc[mi][ni][1] * rs0 * g1);
                *(float2*)&outp[(size_t)(row0 + r + 8) * 64 + nl] =
                    make_float2(acc[mi][ni][2] * rs1 * g0, acc[mi][ni][3] * rs1 * g1);
            }
        }
    }
}

// ============================ prep kernels ============================

__global__ void acoef_k(const float* __restrict__ A_log, float* __restrict__ Ac)
{
    int d = threadIdx.x;
    Ac[d] = -expf(fminf(fmaxf(A_log[d], -20.0f), 2.0f));
}

// [0,8192): round x -> xt (float4/thread). [8192,9280): weight transposes+cvt.
__global__ void __launch_bounds__(256)
prep_k(const float* __restrict__ x,
       const float* __restrict__ Wxp, const float* __restrict__ Wdt,
       const float* __restrict__ Wout, const float* __restrict__ WB,
       const float* __restrict__ WC,
       float* __restrict__ xt, float* __restrict__ Twxp, float* __restrict__ Twdt,
       float* __restrict__ Twout, float* __restrict__ Twbc)
{
    int bid = blockIdx.x;
    if (bid < 8192) {
        const int i = bid * 256 + threadIdx.x;
        float4 v = ((const float4*)x)[i];
        ((uint4*)xt)[i] = make_uint4(f2tf32(v.x), f2tf32(v.y), f2tf32(v.z), f2tf32(v.w));
        return;
    }
    bid -= 8192;
    const float* W; float* Wt; int N, lb;
    if (bid < 512)       { W = Wxp;  Wt = Twxp;            N = 1024; lb = bid; }
    else if (bid < 768)  { W = Wdt;  Wt = Twdt;            N = 512;  lb = bid - 512; }
    else if (bid < 1024) { W = Wout; Wt = Twout;           N = 512;  lb = bid - 768; }
    else if (bid < 1056) { W = WB;   Wt = Twbc;            N = 64;   lb = bid - 1024; }
    else                 { W = WC;   Wt = Twbc + 64 * 512; N = 64;   lb = bid - 1056; }
    const int tiles_n = N / 32;
    const int n0 = (lb % tiles_n) * 32;
    const int k0 = (lb / tiles_n) * 32;
    __shared__ float tile[32][33];
    const int tx = threadIdx.x & 31, ty = threadIdx.x >> 5;
    for (int i = ty; i < 32; i += 8)
        tile[i][tx] = W[(size_t)(k0 + i) * N + n0 + tx];
    __syncthreads();
    for (int i = ty; i < 32; i += 8)
        Wt[(size_t)(n0 + i) * 512 + k0 + tx] = __uint_as_float(f2tf32(tile[tx][i]));
}

// ============================ scan kernels ============================

// Intra-chunk recurrence (f32x2, prefetch). Y gets y_intra + D_skip*x_bar.
__global__ void __launch_bounds__(512)
scan_intra_k(const float* __restrict__ xp, const float* __restrict__ Bm,
             const float* __restrict__ Cm, const float* __restrict__ Dskip,
             float* __restrict__ ax, float* __restrict__ Y,
             float* __restrict__ cs, float* __restrict__ dtot)
{
    __shared__ float4 Bs[64][16];
    __shared__ float4 Cs[64][16];
    const int blk = blockIdx.x;
    const int d = threadIdx.x;
    const size_t l0 = (size_t)blk * 64;

    for (int t = d; t < 64 * 16; t += 512) {
        int r = t >> 4, c = t & 15;
        Bs[r][c] = ((const float4*)Bm)[(l0 + r) * 16 + c];
        Cs[r][c] = ((const float4*)Cm)[(l0 + r) * 16 + c];
    }
    __syncthreads();

    ull S2[32];
    #pragma unroll
    for (int q = 0; q < 32; q++) S2[q] = 0ull;
    float dec = 1.0f;
    const float dsk = Dskip[d];

    const float* axp = ax + l0 * 512 + d;
    const float* xpp = xp + l0 * 1024 + d;
    float av = axp[0];
    float xv = xpp[0];

    #pragma unroll 1
    for (int i = 0; i < 64; i++) {
        float av_n = 0.0f, xv_n = 0.0f;
        if (i < 63) { av_n = axp[(size_t)(i + 1) * 512]; xv_n = xpp[(size_t)(i + 1) * 1024]; }
        const size_t m = l0 + i;
        dec *= av;
        ax[m * 512 + d] = dec;
        const ull av2 = pack2(av, av);
        const ull xv2 = pack2(xv, xv);
        const ull* Bp = (const ull*)&Bs[i][0];
        const ull* Cp = (const ull*)&Cs[i][0];
        ull y2 = 0ull;
        #pragma unroll
        for (int q = 0; q < 32; q++) {
            ull bx; MUL2(bx, Bp[q], xv2);
            FMA2_ACC(bx, av2, S2[q]);   // bx = av*S + b*x
            S2[q] = bx;
            FMA2_ACC(y2, Cp[q], S2[q]);
        }
        float ylo, yhi; unpack2(y2, ylo, yhi);
        Y[m * 512 + d] = ylo + yhi + dsk * xv;
        av = av_n; xv = xv_n;
    }

    #pragma unroll
    for (int q = 0; q < 32; q++) {
        float slo, shi; unpack2(S2[q], slo, shi);
        cs[((size_t)blk * 64 + 2 * q) * 512 + d] = slo;
        cs[((size_t)blk * 64 + 2 * q + 1) * 512 + d] = shi;
    }
    dtot[(size_t)blk * 512 + d] = dec;
}

// Inter-chunk state scan (prefetch), float4 over d; cs -> prev_state in place.
__global__ void state_scan_k(float* __restrict__ cs, const float* __restrict__ dtot)
{
    const int idx = blockIdx.x * blockDim.x + threadIdx.x;   // B*N*128 = 32768
    const int d4 = idx & 127;
    const int n = (idx >> 7) & 63;
    const int b = idx >> 13;
    float4* cs4 = (float4*)cs;
    const float4* dt4 = (const float4*)dtot;
    float4 s = make_float4(0.f, 0.f, 0.f, 0.f);

    size_t off = ((size_t)(b * 64) * 64 + n) * 128 + d4;
    float4 v = cs4[off];
    float4 a = dt4[(size_t)(b * 64) * 128 + d4];

    #pragma unroll 1
    for (int ch = 0; ch < 64; ch++) {
        float4 vn, an;
        if (ch < 63) {
            const int blkn = b * 64 + ch + 1;
            vn = cs4[((size_t)blkn * 64 + n) * 128 + d4];
            an = dt4[(size_t)blkn * 128 + d4];
        } else { vn = s; an = s; }
        cs4[off] = s;
        s.x = fmaf(s.x, a.x, v.x);
        s.y = fmaf(s.y, a.y, v.y);
        s.z = fmaf(s.z, a.z, v.z);
        s.w = fmaf(s.w, a.w, v.w);
        off = ((size_t)(b * 64 + ch + 1) * 64 + n) * 128 + d4;
        v = vn; a = an;
    }
}

// y += decay * (C @ prev_state)   (f32x2; D_skip already folded in scan_intra)
__global__ void __launch_bounds__(512)
yinter_k(const float* __restrict__ Cm, const float* __restrict__ ps,
         const float* __restrict__ decay, float* __restrict__ Y)
{
    __shared__ float4 Cs[64][16];
    const int blk = blockIdx.x;
    const int d = threadIdx.x;
    const size_t l0 = (size_t)blk * 64;

    for (int t = d; t < 64 * 16; t += 512) {
        int r = t >> 4, c = t & 15;
        Cs[r][c] = ((const float4*)Cm)[(l0 + r) * 16 + c];
    }
    __syncthreads();

    ull PS2[32];
    #pragma unroll
    for (int q = 0; q < 32; q++)
        PS2[q] = pack2(ps[((size_t)blk * 64 + 2 * q) * 512 + d],
                       ps[((size_t)blk * 64 + 2 * q + 1) * 512 + d]);

    float dc = decay[l0 * 512 + d];
    float yv = Y[l0 * 512 + d];

    #pragma unroll 1
    for (int i = 0; i < 64; i++) {
        float dc_n = 0.0f, yv_n = 0.0f;
        if (i < 63) {
            dc_n = decay[(l0 + i + 1) * 512 + d];
            yv_n = Y[(l0 + i + 1) * 512 + d];
        }
        const ull* Cp = (const ull*)&Cs[i][0];
        ull y2 = 0ull;
        #pragma unroll
        for (int q = 0; q < 32; q++)
            FMA2_ACC(y2, Cp[q], PS2[q]);
        float ylo, yhi; unpack2(y2, ylo, yhi);
        Y[(l0 + i) * 512 + d] = yv + dc * (ylo + yhi);
        dc = dc_n; yv = yv_n;
    }
}

// h = tf32round(rmsnorm(y, g) * silu(z)), in place over Y.
__global__ void outnorm_k(float* __restrict__ Y, const float* __restrict__ xp,
                          const float* __restrict__ g)
{
    __shared__ float red[256];
    const int m = blockIdx.x;
    const int t = threadIdx.x;
    float v0 = Y[(size_t)m * 512 + t];
    float v1 = Y[(size_t)m * 512 + t + 256];
    red[t] = v0 * v0 + v1 * v1;
    __syncthreads();
    for (int s = 128; s > 0; s >>= 1) {
        if (t < s) red[t] += red[t + s];
        __syncthreads();
    }
    float rs = rsqrtf(red[0] * (1.0f / 512.0f) + 1e-6f);
    float z0 = xp[(size_t)m * 1024 + 512 + t];
    float z1 = xp[(size_t)m * 1024 + 512 + t + 256];
    float s0 = z0 / (1.0f + expf(-z0));
    float s1 = z1 / (1.0f + expf(-z1));
    Y[(size_t)m * 512 + t]       = __uint_as_float(f2tf32(v0 * rs * g[t] * s0));
    Y[(size_t)m * 512 + t + 256] = __uint_as_float(f2tf32(v1 * rs * g[t + 256] * s1));
}

// ============================ launch ============================
#define GEMM_SMEM 73728

extern "C" void kernel_launch(void* const* d_in, const int* in_sizes, int n_in,
                              void* d_out, int out_size)
{
    const float* x       = (const float*)d_in[0];
    const float* A_log   = (const float*)d_in[1];
    const float* dt_bias = (const float*)d_in[2];
    const float* D_skip  = (const float*)d_in[3];
    const float* W_xproj = (const float*)d_in[4];
    const float* b_xproj = (const float*)d_in[5];
    const float* W_B     = (const float*)d_in[6];
    const float* W_C     = (const float*)d_in[7];
    const float* W_dt    = (const float*)d_in[8];
    const float* g_Bn    = (const float*)d_in[9];
    const float* g_Cn    = (const float*)d_in[10];
    const float* g_on    = (const float*)d_in[11];
    const float* W_out   = (const float*)d_in[12];
    const float* b_out   = (const float*)d_in[13];
    float* out = (float*)d_out;

    float *p_xp, *p_xt, *p_xbt, *p_Bm, *p_Cm, *p_ax, *p_Y, *p_cs, *p_dt, *p_Ac;
    float *p_Wxp, *p_Wdt, *p_Wout, *p_Wbc;
    cudaGetSymbolAddress((void**)&p_xp,  g_xp);
    cudaGetSymbolAddress((void**)&p_xt,  g_xt);
    cudaGetSymbolAddress((void**)&p_xbt, g_xbt);
    cudaGetSymbolAddress((void**)&p_Bm,  g_Bm);
    cudaGetSymbolAddress((void**)&p_Cm,  g_Cm);
    cudaGetSymbolAddress((void**)&p_ax,  g_ax);
    cudaGetSymbolAddress((void**)&p_Y,   g_Yb);
    cudaGetSymbolAddress((void**)&p_cs,  g_cs);
    cudaGetSymbolAddress((void**)&p_dt,  g_dtot);
    cudaGetSymbolAddress((void**)&p_Ac,  g_Ac);
    cudaGetSymbolAddress((void**)&p_Wxp,  g_Wt_xp);
    cudaGetSymbolAddress((void**)&p_Wdt,  g_Wt_dt);
    cudaGetSymbolAddress((void**)&p_Wout, g_Wt_out);
    cudaGetSymbolAddress((void**)&p_Wbc,  g_Wt_bc);

    cudaFuncSetAttribute(mma_gemm_k<0>, cudaFuncAttributeMaxDynamicSharedMemorySize, GEMM_SMEM);
    cudaFuncSetAttribute(mma_gemm_k<3>, cudaFuncAttributeMaxDynamicSharedMemorySize, GEMM_SMEM);
    cudaFuncSetAttribute(dtbc_gemm_k,   cudaFuncAttributeMaxDynamicSharedMemorySize, GEMM_SMEM);

    // 0: A coefficient
    acoef_k<<<1, 512>>>(A_log, p_Ac);
    // 1: weight transposes + x rounding
    prep_k<<<9280, 256>>>(x, W_xproj, W_dt, W_out, W_B, W_C,
                          p_xt, p_Wxp, p_Wdt, p_Wout, p_Wbc);
    // 2: xp = x @ W_xproj + b_xproj (also emits tf32-rounded x_bar)
    mma_gemm_k<3><<<dim3(8, 128), 256, GEMM_SMEM>>>(
        p_xt, 512, p_Wxp, b_xproj, p_xp, p_xbt, 1024);
    // 3: merged dt-GEMM + fused B|C projection + rmsnorm (one wave)
    dtbc_gemm_k<<<dim3(5, 128), 256, GEMM_SMEM>>>(
        p_xbt, p_Wdt, p_Wbc, dt_bias, p_Ac, p_ax, p_Bm, p_Cm, g_Bn, g_Cn);
    // 4: intra-chunk recurrence (+ D_skip*x_bar folded)
    scan_intra_k<<<NBLK, 512>>>(p_xp, p_Bm, p_Cm, D_skip, p_ax, p_Y, p_cs, p_dt);
    // 5: inter-chunk state scan
    state_scan_k<<<(BQ * NQ * 128) / 256, 256>>>(p_cs, p_dt);
    // 6: y += decay * (C @ prev_state)
    yinter_k<<<NBLK, 512>>>(p_Cm, p_cs, p_ax, p_Y);
    // 7: h = rmsnorm(y) * silu(z) (tf32)
    outnorm_k<<<MQ, 256>>>(p_Y, p_xp, g_on);
    // 8: out = h @ W_out + b_out
    mma_gemm_k<0><<<dim3(4, 128), 256, GEMM_SMEM>>>(
        p_Y, 512, p_Wout, b_out, out, nullptr, 512);
}